// round 2
// baseline (speedup 1.0000x reference)
#include <cuda_runtime.h>
#include <math.h>

#define DIM 512
#define D_INNER 1024
#define D_STATE 64
#define DT_RANK 32
#define NXD 160          // DT_RANK + 2*D_STATE
#define BSZ 4
#define SEQ 2048
#define M_TOT (BSZ*SEQ)  // 8192

// ---------------- scratch (device globals; no runtime allocation) ----------
__device__ float g_xn[(size_t)M_TOT*DIM];          // 16 MB
__device__ float g_xz[(size_t)M_TOT*2*D_INNER];    // 64 MB
__device__ float g_xc[(size_t)M_TOT*D_INNER];      // 32 MB
__device__ float g_xdbl[(size_t)M_TOT*NXD];        // 5 MB
__device__ float g_dt[(size_t)M_TOT*D_INNER];      // 32 MB
__device__ float g_y[(size_t)M_TOT*D_INNER];       // 32 MB
__device__ float g_m[(size_t)M_TOT*DIM];           // 16 MB

// ---------------- layernorm (optionally + residual) ------------------------
// one block per row of 512; 256 threads, 2 elements each
__global__ __launch_bounds__(256) void ln_kernel(
    const float* __restrict__ x, const float* __restrict__ w,
    const float* __restrict__ b, const float* __restrict__ resid,
    float* __restrict__ out)
{
    int row = blockIdx.x;
    const float* xr = x + (size_t)row * DIM;
    int tid = threadIdx.x;
    float v0 = xr[tid];
    float v1 = xr[tid + 256];
    float s  = v0 + v1;
    float sq = v0*v0 + v1*v1;
#pragma unroll
    for (int o = 16; o > 0; o >>= 1) {
        s  += __shfl_xor_sync(0xffffffffu, s,  o);
        sq += __shfl_xor_sync(0xffffffffu, sq, o);
    }
    __shared__ float ss[8], ssq[8];
    int wid = tid >> 5, lane = tid & 31;
    if (lane == 0) { ss[wid] = s; ssq[wid] = sq; }
    __syncthreads();
    float st = 0.f, sqt = 0.f;
#pragma unroll
    for (int i = 0; i < 8; i++) { st += ss[i]; sqt += ssq[i]; }
    float mean = st * (1.f / DIM);
    float var  = sqt * (1.f / DIM) - mean * mean;
    float inv  = rsqrtf(var + 1e-5f);
    float r0 = (v0 - mean) * inv * w[tid]       + b[tid];
    float r1 = (v1 - mean) * inv * w[tid + 256] + b[tid + 256];
    if (resid) {
        r0 += resid[(size_t)row*DIM + tid];
        r1 += resid[(size_t)row*DIM + tid + 256];
    }
    out[(size_t)row*DIM + tid]       = r0;
    out[(size_t)row*DIM + tid + 256] = r1;
}

// ---------------- generic fp32 GEMM: C[M,N] = A[M,K] * B[N,K]^T ------------
// BM=BN=128, BK=8, 256 threads, 8x8 per thread. EPI: 0 none, 1 bias+softplus
template<int EPI>
__global__ __launch_bounds__(256) void gemm_tn(
    const float* __restrict__ A, const float* __restrict__ B,
    float* __restrict__ C, const float* __restrict__ bias,
    int M, int N, int K, int lda, int ldb, int ldc)
{
    __shared__ float As[8][128];
    __shared__ float Bs[8][128];
    int tid  = threadIdx.x;
    int bm   = blockIdx.y * 128;
    int bn   = blockIdx.x * 128;
    int lrow = tid >> 1;         // 0..127
    int lk4  = (tid & 1) << 2;   // 0 or 4
    int tr   = tid >> 4;         // 0..15
    int tc   = tid & 15;         // 0..15

    float acc[8][8];
#pragma unroll
    for (int i = 0; i < 8; i++)
#pragma unroll
        for (int j = 0; j < 8; j++) acc[i][j] = 0.f;

    const float* Aptr = A + (size_t)(bm + lrow) * lda + lk4;
    const float* Bptr = B + (size_t)(bn + lrow) * ldb + lk4;
    bool bvalid = (bn + lrow) < N;

    for (int k0 = 0; k0 < K; k0 += 8) {
        float4 av = *(const float4*)(Aptr + k0);
        float4 bv = make_float4(0.f, 0.f, 0.f, 0.f);
        if (bvalid) bv = *(const float4*)(Bptr + k0);
        __syncthreads();
        As[lk4+0][lrow] = av.x; As[lk4+1][lrow] = av.y;
        As[lk4+2][lrow] = av.z; As[lk4+3][lrow] = av.w;
        Bs[lk4+0][lrow] = bv.x; Bs[lk4+1][lrow] = bv.y;
        Bs[lk4+2][lrow] = bv.z; Bs[lk4+3][lrow] = bv.w;
        __syncthreads();
#pragma unroll
        for (int k = 0; k < 8; k++) {
            float4 a0 = *(const float4*)&As[k][tr*8];
            float4 a1 = *(const float4*)&As[k][tr*8 + 4];
            float4 b0 = *(const float4*)&Bs[k][tc*8];
            float4 b1 = *(const float4*)&Bs[k][tc*8 + 4];
            float ar[8] = {a0.x,a0.y,a0.z,a0.w,a1.x,a1.y,a1.z,a1.w};
            float br[8] = {b0.x,b0.y,b0.z,b0.w,b1.x,b1.y,b1.z,b1.w};
#pragma unroll
            for (int i = 0; i < 8; i++)
#pragma unroll
                for (int j = 0; j < 8; j++)
                    acc[i][j] = fmaf(ar[i], br[j], acc[i][j]);
        }
    }
#pragma unroll
    for (int i = 0; i < 8; i++) {
        int r = bm + tr*8 + i;
#pragma unroll
        for (int j = 0; j < 8; j++) {
            int c = bn + tc*8 + j;
            if (c < N) {
                float v = acc[i][j];
                if (EPI == 1) {
                    v += bias[c];
                    v = (v > 0.f) ? v + log1pf(__expf(-v)) : log1pf(__expf(v));
                }
                C[(size_t)r * ldc + c] = v;
            }
        }
    }
}

// ---------------- causal depthwise conv (width 4) + SiLU -------------------
__global__ __launch_bounds__(256) void conv_silu_kernel(
    const float* __restrict__ xz, const float* __restrict__ cw,
    const float* __restrict__ cb, float* __restrict__ xc)
{
    int idx = blockIdx.x * 256 + threadIdx.x;   // [M_TOT * D_INNER), e fastest
    int e = idx & (D_INNER - 1);
    int m = idx >> 10;
    int t = m & (SEQ - 1);
    float4 w = ((const float4*)cw)[e];          // conv_w[e,0,0..3]
    const float* base = xz + (size_t)m * (2*D_INNER) + e;
    float acc = cb[e];
    acc = fmaf(base[0], w.w, acc);
    if (t >= 1) acc = fmaf(base[-(ptrdiff_t)(2*D_INNER)],   w.z, acc);
    if (t >= 2) acc = fmaf(base[-(ptrdiff_t)(4*D_INNER)],   w.y, acc);
    if (t >= 3) acc = fmaf(base[-(ptrdiff_t)(6*D_INNER)],   w.x, acc);
    float sig = 1.f / (1.f + __expf(-acc));
    xc[idx] = acc * sig;
}

// ---------------- selective scan + fused gating epilogue -------------------
// 1 warp per (b, e) channel; lane owns states {2*lane, 2*lane+1}.
// dt/xc/z staged through SMEM in 32-step windows (coalesced).
// Output: yout = (scan_y + D*xc) * silu(z)   in [m, e] layout.
__global__ __launch_bounds__(256) void scan_kernel(
    const float* __restrict__ xdbl, const float* __restrict__ dt,
    const float* __restrict__ xc,   const float* __restrict__ xz,
    const float* __restrict__ A_log, const float* __restrict__ Dp,
    float* __restrict__ yout)
{
    __shared__ float sdt[32*8], sxc[32*8], sz[32*8], sy[32*8];
    int tid  = threadIdx.x;
    int b    = blockIdx.x >> 7;
    int e0   = (blockIdx.x & 127) << 3;
    int w    = tid >> 5;
    int lane = tid & 31;
    int e    = e0 + w;

    float A0 = -__expf(A_log[e*64 + 2*lane]);
    float A1 = -__expf(A_log[e*64 + 2*lane + 1]);
    float h0 = 0.f, h1 = 0.f;

    int tload = tid >> 3;   // 0..31 (time within window)
    int eload = tid & 7;    // 0..7  (channel within group)
    size_t mbase = (size_t)b * SEQ;

    for (int t0 = 0; t0 < SEQ; t0 += 32) {
        size_t mrow = mbase + t0 + tload;
        sdt[tid] = dt[mrow * D_INNER + e0 + eload];
        sxc[tid] = xc[mrow * D_INNER + e0 + eload];
        sz[tid]  = xz[mrow * (2*D_INNER) + D_INNER + e0 + eload];
        __syncthreads();

        const float* xrow = xdbl + (mbase + t0) * NXD;
#pragma unroll 4
        for (int i = 0; i < 32; i++) {
            float dtv = sdt[i*8 + w];
            float xv  = sxc[i*8 + w];
            float2 Bv = *(const float2*)(xrow + DT_RANK + 2*lane);
            float2 Cv = *(const float2*)(xrow + DT_RANK + D_STATE + 2*lane);
            xrow += NXD;
            float du = dtv * xv;
            float g0 = __expf(dtv * A0);
            float g1 = __expf(dtv * A1);
            h0 = fmaf(g0, h0, du * Bv.x);
            h1 = fmaf(g1, h1, du * Bv.y);
            float p = fmaf(h0, Cv.x, h1 * Cv.y);
            p += __shfl_xor_sync(0xffffffffu, p, 16);
            p += __shfl_xor_sync(0xffffffffu, p, 8);
            p += __shfl_xor_sync(0xffffffffu, p, 4);
            p += __shfl_xor_sync(0xffffffffu, p, 2);
            p += __shfl_xor_sync(0xffffffffu, p, 1);
            if (lane == 0) sy[i*8 + w] = p;
        }
        __syncthreads();

        // fused epilogue: (y + D*xc) * silu(z), coalesced writeback
        {
            float yv  = sy[tid];
            float xcv = sxc[tid];
            float zv  = sz[tid];
            float Dv  = Dp[e0 + eload];
            float r   = fmaf(Dv, xcv, yv);
            float sig = 1.f / (1.f + __expf(-zv));
            r = r * zv * sig;
            yout[mrow * D_INNER + e0 + eload] = r;
        }
        __syncthreads();
    }
}

// ---------------- host launch ----------------------------------------------
extern "C" void kernel_launch(void* const* d_in, const int* in_sizes, int n_in,
                              void* d_out, int out_size)
{
    const float* x         = (const float*)d_in[0];
    const float* ln_m_w    = (const float*)d_in[1];
    const float* ln_m_b    = (const float*)d_in[2];
    const float* ln1_w     = (const float*)d_in[3];
    const float* ln1_b     = (const float*)d_in[4];
    const float* in_proj_w = (const float*)d_in[5];
    const float* conv_w    = (const float*)d_in[6];
    const float* conv_b    = (const float*)d_in[7];
    const float* x_proj_w  = (const float*)d_in[8];
    const float* dt_proj_w = (const float*)d_in[9];
    const float* dt_proj_b = (const float*)d_in[10];
    const float* A_log     = (const float*)d_in[11];
    const float* D_param   = (const float*)d_in[12];
    const float* out_proj_w= (const float*)d_in[13];
    float* out = (float*)d_out;

    float *xn, *xz, *xc, *xdbl, *dtp, *y, *m;
    cudaGetSymbolAddress((void**)&xn,   g_xn);
    cudaGetSymbolAddress((void**)&xz,   g_xz);
    cudaGetSymbolAddress((void**)&xc,   g_xc);
    cudaGetSymbolAddress((void**)&xdbl, g_xdbl);
    cudaGetSymbolAddress((void**)&dtp,  g_dt);
    cudaGetSymbolAddress((void**)&y,    g_y);
    cudaGetSymbolAddress((void**)&m,    g_m);

    // 1. xn = LN(x)
    ln_kernel<<<M_TOT, 256>>>(x, ln_m_w, ln_m_b, nullptr, xn);

    // 2. xz = xn @ in_proj_w^T   [8192, 2048]
    {
        dim3 g(2*D_INNER/128, M_TOT/128);
        gemm_tn<0><<<g, 256>>>(xn, in_proj_w, xz, nullptr,
                               M_TOT, 2*D_INNER, DIM, DIM, DIM, 2*D_INNER);
    }

    // 3. xc = silu(causal_conv(xp) + b)   [8192, 1024]
    conv_silu_kernel<<<(M_TOT*D_INNER)/256, 256>>>(xz, conv_w, conv_b, xc);

    // 4. x_dbl = xc @ x_proj_w^T   [8192, 160]
    {
        dim3 g((NXD + 127)/128, M_TOT/128);
        gemm_tn<0><<<g, 256>>>(xc, x_proj_w, xdbl, nullptr,
                               M_TOT, NXD, D_INNER, D_INNER, D_INNER, NXD);
    }

    // 5. dt = softplus(dt_r @ dt_proj_w^T + dt_proj_b)   [8192, 1024]
    {
        dim3 g(D_INNER/128, M_TOT/128);
        gemm_tn<1><<<g, 256>>>(xdbl, dt_proj_w, dtp, dt_proj_b,
                               M_TOT, D_INNER, DT_RANK, NXD, DT_RANK, D_INNER);
    }

    // 6. selective scan + (y + D*xc)*silu(z)   [8192, 1024]
    scan_kernel<<<BSZ*128, 256>>>(xdbl, dtp, xc, xz, A_log, D_param, y);

    // 7. m = y @ out_proj_w^T   [8192, 512]
    {
        dim3 g(DIM/128, M_TOT/128);
        gemm_tn<0><<<g, 256>>>(y, out_proj_w, m, nullptr,
                               M_TOT, DIM, D_INNER, D_INNER, D_INNER, DIM);
    }

    // 8. out = x + LN(m)
    ln_kernel<<<M_TOT, 256>>>(m, ln1_w, ln1_b, x, out);
}

// round 7
// speedup vs baseline: 1.4317x; 1.4317x over previous
#include <cuda_runtime.h>
#include <math.h>
#include <stdint.h>

#define DIM 512
#define D_INNER 1024
#define D_STATE 64
#define DT_RANK 32
#define NXD 160          // DT_RANK + 2*D_STATE
#define BSZ 4
#define SEQ 2048
#define M_TOT (BSZ*SEQ)  // 8192

// ---------------- scratch (device globals; no runtime allocation) ----------
__device__ float g_xn[(size_t)M_TOT*DIM];
__device__ float g_xz[(size_t)M_TOT*2*D_INNER];
__device__ float g_xc[(size_t)M_TOT*D_INNER];
__device__ float g_xdbl[(size_t)M_TOT*NXD];
__device__ float g_dt[(size_t)M_TOT*D_INNER];
__device__ float g_y[(size_t)M_TOT*D_INNER];
__device__ float g_m[(size_t)M_TOT*DIM];

// ---------------- layernorm (optionally + residual) ------------------------
__global__ __launch_bounds__(256) void ln_kernel(
    const float* __restrict__ x, const float* __restrict__ w,
    const float* __restrict__ b, const float* __restrict__ resid,
    float* __restrict__ out)
{
    int row = blockIdx.x;
    const float* xr = x + (size_t)row * DIM;
    int tid = threadIdx.x;
    float v0 = xr[tid];
    float v1 = xr[tid + 256];
    float s  = v0 + v1;
    float sq = v0*v0 + v1*v1;
#pragma unroll
    for (int o = 16; o > 0; o >>= 1) {
        s  += __shfl_xor_sync(0xffffffffu, s,  o);
        sq += __shfl_xor_sync(0xffffffffu, sq, o);
    }
    __shared__ float ss[8], ssq[8];
    int wid = tid >> 5, lane = tid & 31;
    if (lane == 0) { ss[wid] = s; ssq[wid] = sq; }
    __syncthreads();
    float st = 0.f, sqt = 0.f;
#pragma unroll
    for (int i = 0; i < 8; i++) { st += ss[i]; sqt += ssq[i]; }
    float mean = st * (1.f / DIM);
    float var  = sqt * (1.f / DIM) - mean * mean;
    float inv  = rsqrtf(var + 1e-5f);
    float r0 = (v0 - mean) * inv * w[tid]       + b[tid];
    float r1 = (v1 - mean) * inv * w[tid + 256] + b[tid + 256];
    if (resid) {
        r0 += resid[(size_t)row*DIM + tid];
        r1 += resid[(size_t)row*DIM + tid + 256];
    }
    out[(size_t)row*DIM + tid]       = r0;
    out[(size_t)row*DIM + tid + 256] = r1;
}

// ================= tf32 tensor-core GEMM: C[M,N] = A[M,K] * B[N,K]^T =======
// BM=BN=128, BK=16, 256 threads (8 warps, 4x2), warp tile 32x64.
// Requires M%128==0, N%128==0, K%16==0. cp.async double-buffered.
#define KSTRIDE 20   // 16 + 4 pad: bank = (row*20 + k) % 32 -> conflict-free

__device__ __forceinline__ unsigned smem_addr_u32(const void* p) {
    return (unsigned)__cvta_generic_to_shared(p);
}
__device__ __forceinline__ void cp_async16(unsigned dst, const float* src) {
    asm volatile("cp.async.cg.shared.global [%0], [%1], 16;\n" :: "r"(dst), "l"(src));
}
__device__ __forceinline__ void mma_tf32(float* d, const uint32_t* a, const uint32_t* b) {
    asm volatile(
        "mma.sync.aligned.m16n8k8.row.col.f32.tf32.tf32.f32 "
        "{%0,%1,%2,%3}, {%4,%5,%6,%7}, {%8,%9}, {%0,%1,%2,%3};"
        : "+f"(d[0]), "+f"(d[1]), "+f"(d[2]), "+f"(d[3])
        : "r"(a[0]), "r"(a[1]), "r"(a[2]), "r"(a[3]), "r"(b[0]), "r"(b[1]));
}

__global__ __launch_bounds__(256, 2) void gemm_tf32(
    const float* __restrict__ A, const float* __restrict__ B,
    float* __restrict__ C, int K, int lda, int ldb, int ldc)
{
    __shared__ float As[2][128][KSTRIDE];
    __shared__ float Bs[2][128][KSTRIDE];

    int tid  = threadIdx.x;
    int bm   = blockIdx.y * 128;
    int bn   = blockIdx.x * 128;
    int w    = tid >> 5, lane = tid & 31;
    int wm   = w & 3;           // 0..3 -> m offset wm*32
    int wn   = w >> 2;          // 0..1 -> n offset wn*64
    int gid  = lane >> 2;       // 0..7
    int tq   = lane & 3;        // 0..3

    // global load mapping: row = tid>>1 (0..127), (tid&1) picks 8-float half
    int lrow = tid >> 1;
    int lk   = (tid & 1) * 8;
    const float* Ag = A + (size_t)(bm + lrow) * lda + lk;
    const float* Bg = B + (size_t)(bn + lrow) * ldb + lk;

    float acc[2][8][4];
#pragma unroll
    for (int i = 0; i < 2; i++)
#pragma unroll
        for (int j = 0; j < 8; j++)
#pragma unroll
            for (int q = 0; q < 4; q++) acc[i][j][q] = 0.f;

    int T = K / 16;

    // prefetch tile 0 into buffer 0
    {
        unsigned da0 = smem_addr_u32(&As[0][lrow][lk]);
        unsigned db0 = smem_addr_u32(&Bs[0][lrow][lk]);
        cp_async16(da0,     Ag);
        cp_async16(da0 + 16, Ag + 4);
        cp_async16(db0,     Bg);
        cp_async16(db0 + 16, Bg + 4);
        asm volatile("cp.async.commit_group;\n");
    }

    for (int t = 0; t < T; t++) {
        int s = t & 1;
        // prefetch next (or commit empty group to keep wait count uniform)
        if (t + 1 < T) {
            const float* an = Ag + (size_t)(t + 1) * 16;
            const float* bnp = Bg + (size_t)(t + 1) * 16;
            unsigned da = smem_addr_u32(&As[s ^ 1][lrow][lk]);
            unsigned db = smem_addr_u32(&Bs[s ^ 1][lrow][lk]);
            cp_async16(da,      an);
            cp_async16(da + 16, an + 4);
            cp_async16(db,      bnp);
            cp_async16(db + 16, bnp + 4);
        }
        asm volatile("cp.async.commit_group;\n");
        asm volatile("cp.async.wait_group 1;\n");
        __syncthreads();

#pragma unroll
        for (int kk = 0; kk < 2; kk++) {
            int k0 = kk * 8;
            uint32_t af[2][4];
            uint32_t bf[8][2];
#pragma unroll
            for (int mt = 0; mt < 2; mt++) {
                int m = wm * 32 + mt * 16;
                af[mt][0] = __float_as_uint(As[s][m + gid    ][k0 + tq]);
                af[mt][1] = __float_as_uint(As[s][m + gid + 8][k0 + tq]);
                af[mt][2] = __float_as_uint(As[s][m + gid    ][k0 + tq + 4]);
                af[mt][3] = __float_as_uint(As[s][m + gid + 8][k0 + tq + 4]);
            }
#pragma unroll
            for (int nt = 0; nt < 8; nt++) {
                int n = wn * 64 + nt * 8;
                bf[nt][0] = __float_as_uint(Bs[s][n + gid][k0 + tq]);
                bf[nt][1] = __float_as_uint(Bs[s][n + gid][k0 + tq + 4]);
            }
#pragma unroll
            for (int mt = 0; mt < 2; mt++)
#pragma unroll
                for (int nt = 0; nt < 8; nt++)
                    mma_tf32(acc[mt][nt], af[mt], bf[nt]);
        }
        __syncthreads();
    }

    // epilogue
#pragma unroll
    for (int mt = 0; mt < 2; mt++) {
        int r0 = bm + wm * 32 + mt * 16 + gid;
#pragma unroll
        for (int nt = 0; nt < 8; nt++) {
            int c = bn + wn * 64 + nt * 8 + tq * 2;
            float2 v01 = make_float2(acc[mt][nt][0], acc[mt][nt][1]);
            float2 v23 = make_float2(acc[mt][nt][2], acc[mt][nt][3]);
            *(float2*)&C[(size_t)r0 * ldc + c]       = v01;
            *(float2*)&C[(size_t)(r0 + 8) * ldc + c] = v23;
        }
    }
}

// ---------------- generic fp32 GEMM (kept for x_proj / dt_proj: accuracy) --
template<int EPI>
__global__ __launch_bounds__(256) void gemm_tn(
    const float* __restrict__ A, const float* __restrict__ B,
    float* __restrict__ C, const float* __restrict__ bias,
    int M, int N, int K, int lda, int ldb, int ldc)
{
    __shared__ float As[8][128];
    __shared__ float Bs[8][128];
    int tid  = threadIdx.x;
    int bm   = blockIdx.y * 128;
    int bn   = blockIdx.x * 128;
    int lrow = tid >> 1;
    int lk4  = (tid & 1) << 2;
    int tr   = tid >> 4;
    int tc   = tid & 15;

    float acc[8][8];
#pragma unroll
    for (int i = 0; i < 8; i++)
#pragma unroll
        for (int j = 0; j < 8; j++) acc[i][j] = 0.f;

    const float* Aptr = A + (size_t)(bm + lrow) * lda + lk4;
    const float* Bptr = B + (size_t)(bn + lrow) * ldb + lk4;
    bool bvalid = (bn + lrow) < N;

    for (int k0 = 0; k0 < K; k0 += 8) {
        float4 av = *(const float4*)(Aptr + k0);
        float4 bv = make_float4(0.f, 0.f, 0.f, 0.f);
        if (bvalid) bv = *(const float4*)(Bptr + k0);
        __syncthreads();
        As[lk4+0][lrow] = av.x; As[lk4+1][lrow] = av.y;
        As[lk4+2][lrow] = av.z; As[lk4+3][lrow] = av.w;
        Bs[lk4+0][lrow] = bv.x; Bs[lk4+1][lrow] = bv.y;
        Bs[lk4+2][lrow] = bv.z; Bs[lk4+3][lrow] = bv.w;
        __syncthreads();
#pragma unroll
        for (int k = 0; k < 8; k++) {
            float4 a0 = *(const float4*)&As[k][tr*8];
            float4 a1 = *(const float4*)&As[k][tr*8 + 4];
            float4 b0 = *(const float4*)&Bs[k][tc*8];
            float4 b1 = *(const float4*)&Bs[k][tc*8 + 4];
            float ar[8] = {a0.x,a0.y,a0.z,a0.w,a1.x,a1.y,a1.z,a1.w};
            float br[8] = {b0.x,b0.y,b0.z,b0.w,b1.x,b1.y,b1.z,b1.w};
#pragma unroll
            for (int i = 0; i < 8; i++)
#pragma unroll
                for (int j = 0; j < 8; j++)
                    acc[i][j] = fmaf(ar[i], br[j], acc[i][j]);
        }
    }
#pragma unroll
    for (int i = 0; i < 8; i++) {
        int r = bm + tr*8 + i;
#pragma unroll
        for (int j = 0; j < 8; j++) {
            int c = bn + tc*8 + j;
            if (c < N) {
                float v = acc[i][j];
                if (EPI == 1) {
                    v += bias[c];
                    v = (v > 0.f) ? v + log1pf(__expf(-v)) : log1pf(__expf(v));
                }
                C[(size_t)r * ldc + c] = v;
            }
        }
    }
}

// ---------------- causal depthwise conv (width 4) + SiLU -------------------
__global__ __launch_bounds__(256) void conv_silu_kernel(
    const float* __restrict__ xz, const float* __restrict__ cw,
    const float* __restrict__ cb, float* __restrict__ xc)
{
    int idx = blockIdx.x * 256 + threadIdx.x;
    int e = idx & (D_INNER - 1);
    int m = idx >> 10;
    int t = m & (SEQ - 1);
    float4 w = ((const float4*)cw)[e];
    const float* base = xz + (size_t)m * (2*D_INNER) + e;
    float acc = cb[e];
    acc = fmaf(base[0], w.w, acc);
    if (t >= 1) acc = fmaf(base[-(ptrdiff_t)(2*D_INNER)], w.z, acc);
    if (t >= 2) acc = fmaf(base[-(ptrdiff_t)(4*D_INNER)], w.y, acc);
    if (t >= 3) acc = fmaf(base[-(ptrdiff_t)(6*D_INNER)], w.x, acc);
    float sig = 1.f / (1.f + __expf(-acc));
    xc[idx] = acc * sig;
}

// ---------------- selective scan + fused gating epilogue -------------------
__global__ __launch_bounds__(256) void scan_kernel(
    const float* __restrict__ xdbl, const float* __restrict__ dt,
    const float* __restrict__ xc,   const float* __restrict__ xz,
    const float* __restrict__ A_log, const float* __restrict__ Dp,
    float* __restrict__ yout)
{
    __shared__ float sdt[32*8], sxc[32*8], sz[32*8], sy[32*8];
    int tid  = threadIdx.x;
    int b    = blockIdx.x >> 7;
    int e0   = (blockIdx.x & 127) << 3;
    int w    = tid >> 5;
    int lane = tid & 31;
    int e    = e0 + w;

    float A0 = -__expf(A_log[e*64 + 2*lane]);
    float A1 = -__expf(A_log[e*64 + 2*lane + 1]);
    float h0 = 0.f, h1 = 0.f;

    int tload = tid >> 3;
    int eload = tid & 7;
    size_t mbase = (size_t)b * SEQ;

    for (int t0 = 0; t0 < SEQ; t0 += 32) {
        size_t mrow = mbase + t0 + tload;
        sdt[tid] = dt[mrow * D_INNER + e0 + eload];
        sxc[tid] = xc[mrow * D_INNER + e0 + eload];
        sz[tid]  = xz[mrow * (2*D_INNER) + D_INNER + e0 + eload];
        __syncthreads();

        const float* xrow = xdbl + (mbase + t0) * NXD;
#pragma unroll 4
        for (int i = 0; i < 32; i++) {
            float dtv = sdt[i*8 + w];
            float xv  = sxc[i*8 + w];
            float2 Bv = *(const float2*)(xrow + DT_RANK + 2*lane);
            float2 Cv = *(const float2*)(xrow + DT_RANK + D_STATE + 2*lane);
            xrow += NXD;
            float du = dtv * xv;
            float g0 = __expf(dtv * A0);
            float g1 = __expf(dtv * A1);
            h0 = fmaf(g0, h0, du * Bv.x);
            h1 = fmaf(g1, h1, du * Bv.y);
            float p = fmaf(h0, Cv.x, h1 * Cv.y);
            p += __shfl_xor_sync(0xffffffffu, p, 16);
            p += __shfl_xor_sync(0xffffffffu, p, 8);
            p += __shfl_xor_sync(0xffffffffu, p, 4);
            p += __shfl_xor_sync(0xffffffffu, p, 2);
            p += __shfl_xor_sync(0xffffffffu, p, 1);
            if (lane == 0) sy[i*8 + w] = p;
        }
        __syncthreads();

        {
            float yv  = sy[tid];
            float xcv = sxc[tid];
            float zv  = sz[tid];
            float Dv  = Dp[e0 + eload];
            float r   = fmaf(Dv, xcv, yv);
            float sig = 1.f / (1.f + __expf(-zv));
            r = r * zv * sig;
            yout[mrow * D_INNER + e0 + eload] = r;
        }
        __syncthreads();
    }
}

// ---------------- host launch ----------------------------------------------
extern "C" void kernel_launch(void* const* d_in, const int* in_sizes, int n_in,
                              void* d_out, int out_size)
{
    const float* x         = (const float*)d_in[0];
    const float* ln_m_w    = (const float*)d_in[1];
    const float* ln_m_b    = (const float*)d_in[2];
    const float* ln1_w     = (const float*)d_in[3];
    const float* ln1_b     = (const float*)d_in[4];
    const float* in_proj_w = (const float*)d_in[5];
    const float* conv_w    = (const float*)d_in[6];
    const float* conv_b    = (const float*)d_in[7];
    const float* x_proj_w  = (const float*)d_in[8];
    const float* dt_proj_w = (const float*)d_in[9];
    const float* dt_proj_b = (const float*)d_in[10];
    const float* A_log     = (const float*)d_in[11];
    const float* D_param   = (const float*)d_in[12];
    const float* out_proj_w= (const float*)d_in[13];
    float* out = (float*)d_out;

    float *xn, *xz, *xc, *xdbl, *dtp, *y, *m;
    cudaGetSymbolAddress((void**)&xn,   g_xn);
    cudaGetSymbolAddress((void**)&xz,   g_xz);
    cudaGetSymbolAddress((void**)&xc,   g_xc);
    cudaGetSymbolAddress((void**)&xdbl, g_xdbl);
    cudaGetSymbolAddress((void**)&dtp,  g_dt);
    cudaGetSymbolAddress((void**)&y,    g_y);
    cudaGetSymbolAddress((void**)&m,    g_m);

    // 1. xn = LN(x)
    ln_kernel<<<M_TOT, 256>>>(x, ln_m_w, ln_m_b, nullptr, xn);

    // 2. xz = xn @ in_proj_w^T   [8192, 2048], K=512  (tf32 tensor cores)
    {
        dim3 g(2*D_INNER/128, M_TOT/128);
        gemm_tf32<<<g, 256>>>(xn, in_proj_w, xz, DIM, DIM, DIM, 2*D_INNER);
    }

    // 3. xc = silu(causal_conv(xp) + b)
    conv_silu_kernel<<<(M_TOT*D_INNER)/256, 256>>>(xz, conv_w, conv_b, xc);

    // 4. x_dbl = xc @ x_proj_w^T   [8192, 160]  (fp32: feeds dt, protect precision)
    {
        dim3 g((NXD + 127)/128, M_TOT/128);
        gemm_tn<0><<<g, 256>>>(xc, x_proj_w, xdbl, nullptr,
                               M_TOT, NXD, D_INNER, D_INNER, D_INNER, NXD);
    }

    // 5. dt = softplus(dt_r @ dt_proj_w^T + b)   [8192, 1024]  (fp32)
    {
        dim3 g(D_INNER/128, M_TOT/128);
        gemm_tn<1><<<g, 256>>>(xdbl, dt_proj_w, dtp, dt_proj_b,
                               M_TOT, D_INNER, DT_RANK, NXD, DT_RANK, D_INNER);
    }

    // 6. selective scan + gating
    scan_kernel<<<BSZ*128, 256>>>(xdbl, dtp, xc, xz, A_log, D_param, y);

    // 7. m = y @ out_proj_w^T   [8192, 512], K=1024  (tf32 tensor cores)
    {
        dim3 g(DIM/128, M_TOT/128);
        gemm_tf32<<<g, 256>>>(y, out_proj_w, m, D_INNER, D_INNER, D_INNER, DIM);
    }

    // 8. out = x + LN(m)
    ln_kernel<<<M_TOT, 256>>>(m, ln1_w, ln1_b, x, out);
}

// round 10
// speedup vs baseline: 1.6324x; 1.1401x over previous
#include <cuda_runtime.h>
#include <math.h>
#include <stdint.h>

#define DIM 512
#define D_INNER 1024
#define D_STATE 64
#define DT_RANK 32
#define NXD 160          // DT_RANK + 2*D_STATE
#define BSZ 4
#define SEQ 2048
#define M_TOT (BSZ*SEQ)  // 8192

// ---------------- scratch (device globals; no runtime allocation) ----------
__device__ float g_xn[(size_t)M_TOT*DIM];
__device__ float g_xz[(size_t)M_TOT*2*D_INNER];
__device__ float g_xc[(size_t)M_TOT*D_INNER];
__device__ float g_xdbl[(size_t)M_TOT*NXD];
__device__ float g_dt[(size_t)M_TOT*D_INNER];
__device__ float g_y[(size_t)M_TOT*D_INNER];
__device__ float g_m[(size_t)M_TOT*DIM];

// ---------------- layernorm (optionally + residual) ------------------------
__global__ __launch_bounds__(256) void ln_kernel(
    const float* __restrict__ x, const float* __restrict__ w,
    const float* __restrict__ b, const float* __restrict__ resid,
    float* __restrict__ out)
{
    int row = blockIdx.x;
    const float* xr = x + (size_t)row * DIM;
    int tid = threadIdx.x;
    float v0 = xr[tid];
    float v1 = xr[tid + 256];
    float s  = v0 + v1;
    float sq = v0*v0 + v1*v1;
#pragma unroll
    for (int o = 16; o > 0; o >>= 1) {
        s  += __shfl_xor_sync(0xffffffffu, s,  o);
        sq += __shfl_xor_sync(0xffffffffu, sq, o);
    }
    __shared__ float ss[8], ssq[8];
    int wid = tid >> 5, lane = tid & 31;
    if (lane == 0) { ss[wid] = s; ssq[wid] = sq; }
    __syncthreads();
    float st = 0.f, sqt = 0.f;
#pragma unroll
    for (int i = 0; i < 8; i++) { st += ss[i]; sqt += ssq[i]; }
    float mean = st * (1.f / DIM);
    float var  = sqt * (1.f / DIM) - mean * mean;
    float inv  = rsqrtf(var + 1e-5f);
    float r0 = (v0 - mean) * inv * w[tid]       + b[tid];
    float r1 = (v1 - mean) * inv * w[tid + 256] + b[tid + 256];
    if (resid) {
        r0 += resid[(size_t)row*DIM + tid];
        r1 += resid[(size_t)row*DIM + tid + 256];
    }
    out[(size_t)row*DIM + tid]       = r0;
    out[(size_t)row*DIM + tid + 256] = r1;
}

// ================= tf32 tensor-core GEMM v2 ================================
// C[M,N] = A[M,K] * B[N,K]^T. BM=BN=128, BK=16, 256 threads (8 warps, 4x2),
// warp tile 32x64. 3-stage cp.async pipeline, ONE __syncthreads per k-tile.
// Requires M%128==0, N%128==0, K%16==0. Dynamic smem: 61440 bytes.
#define KSTRIDE 20   // 16 + 4 pad: (row*20 + k) % 32 covers all banks
#define STAGES 3
#define GEMM_SMEM (STAGES * 128 * KSTRIDE * 4 * 2)

__device__ __forceinline__ unsigned smem_addr_u32(const void* p) {
    return (unsigned)__cvta_generic_to_shared(p);
}
__device__ __forceinline__ void cp_async16(unsigned dst, const float* src) {
    asm volatile("cp.async.cg.shared.global [%0], [%1], 16;\n" :: "r"(dst), "l"(src));
}
__device__ __forceinline__ void mma_tf32(float* d, const uint32_t* a, const uint32_t* b) {
    asm volatile(
        "mma.sync.aligned.m16n8k8.row.col.f32.tf32.tf32.f32 "
        "{%0,%1,%2,%3}, {%4,%5,%6,%7}, {%8,%9}, {%0,%1,%2,%3};"
        : "+f"(d[0]), "+f"(d[1]), "+f"(d[2]), "+f"(d[3])
        : "r"(a[0]), "r"(a[1]), "r"(a[2]), "r"(a[3]), "r"(b[0]), "r"(b[1]));
}

__global__ __launch_bounds__(256, 2) void gemm_tf32(
    const float* __restrict__ A, const float* __restrict__ B,
    float* __restrict__ C, int K, int lda, int ldb, int ldc)
{
    extern __shared__ float sm[];
    float (*As)[128][KSTRIDE] = (float(*)[128][KSTRIDE])sm;
    float (*Bs)[128][KSTRIDE] = (float(*)[128][KSTRIDE])(sm + STAGES*128*KSTRIDE);

    int tid  = threadIdx.x;
    int bm   = blockIdx.y * 128;
    int bn   = blockIdx.x * 128;
    int w    = tid >> 5, lane = tid & 31;
    int wm   = w & 3;
    int wn   = w >> 2;
    int gid  = lane >> 2;
    int tq   = lane & 3;

    int lrow = tid >> 1;
    int lk   = (tid & 1) * 8;
    const float* Ag = A + (size_t)(bm + lrow) * lda + lk;
    const float* Bg = B + (size_t)(bn + lrow) * ldb + lk;

    float acc[2][8][4];
#pragma unroll
    for (int i = 0; i < 2; i++)
#pragma unroll
        for (int j = 0; j < 8; j++)
#pragma unroll
            for (int q = 0; q < 4; q++) acc[i][j][q] = 0.f;

    int T = K / 16;

    // prefetch stages 0..STAGES-2
#pragma unroll
    for (int pf = 0; pf < STAGES - 1; pf++) {
        unsigned da = smem_addr_u32(&As[pf][lrow][lk]);
        unsigned db = smem_addr_u32(&Bs[pf][lrow][lk]);
        const float* ap = Ag + (size_t)pf * 16;
        const float* bp = Bg + (size_t)pf * 16;
        cp_async16(da,      ap);
        cp_async16(da + 16, ap + 4);
        cp_async16(db,      bp);
        cp_async16(db + 16, bp + 4);
        asm volatile("cp.async.commit_group;\n");
    }

    for (int t = 0; t < T; t++) {
        int s = t % STAGES;
        asm volatile("cp.async.wait_group %0;\n" :: "n"(STAGES - 2));
        __syncthreads();

        int tp = t + STAGES - 1;
        if (tp < T) {
            int sp = tp % STAGES;
            const float* ap = Ag + (size_t)tp * 16;
            const float* bp = Bg + (size_t)tp * 16;
            unsigned da = smem_addr_u32(&As[sp][lrow][lk]);
            unsigned db = smem_addr_u32(&Bs[sp][lrow][lk]);
            cp_async16(da,      ap);
            cp_async16(da + 16, ap + 4);
            cp_async16(db,      bp);
            cp_async16(db + 16, bp + 4);
        }
        asm volatile("cp.async.commit_group;\n");

#pragma unroll
        for (int kk = 0; kk < 2; kk++) {
            int k0 = kk * 8;
            uint32_t af[2][4];
            uint32_t bf[8][2];
#pragma unroll
            for (int mt = 0; mt < 2; mt++) {
                int m = wm * 32 + mt * 16;
                af[mt][0] = __float_as_uint(As[s][m + gid    ][k0 + tq]);
                af[mt][1] = __float_as_uint(As[s][m + gid + 8][k0 + tq]);
                af[mt][2] = __float_as_uint(As[s][m + gid    ][k0 + tq + 4]);
                af[mt][3] = __float_as_uint(As[s][m + gid + 8][k0 + tq + 4]);
            }
#pragma unroll
            for (int nt = 0; nt < 8; nt++) {
                int n = wn * 64 + nt * 8;
                bf[nt][0] = __float_as_uint(Bs[s][n + gid][k0 + tq]);
                bf[nt][1] = __float_as_uint(Bs[s][n + gid][k0 + tq + 4]);
            }
#pragma unroll
            for (int mt = 0; mt < 2; mt++)
#pragma unroll
                for (int nt = 0; nt < 8; nt++)
                    mma_tf32(acc[mt][nt], af[mt], bf[nt]);
        }
    }

#pragma unroll
    for (int mt = 0; mt < 2; mt++) {
        int r0 = bm + wm * 32 + mt * 16 + gid;
#pragma unroll
        for (int nt = 0; nt < 8; nt++) {
            int c = bn + wn * 64 + nt * 8 + tq * 2;
            float2 v01 = make_float2(acc[mt][nt][0], acc[mt][nt][1]);
            float2 v23 = make_float2(acc[mt][nt][2], acc[mt][nt][3]);
            *(float2*)&C[(size_t)r0 * ldc + c]       = v01;
            *(float2*)&C[(size_t)(r0 + 8) * ldc + c] = v23;
        }
    }
}

// ---------------- dt_r fp32 kernel: xdbl[:, 0:32] = xc @ x_proj_w[0:32]^T --
// 1 warp = 4 rows x 8 cols; lane strides K by 32. Full-chip grid (1024 CTAs).
__global__ __launch_bounds__(256) void dtr_kernel(
    const float* __restrict__ A,   // xc [M_TOT, 1024]
    const float* __restrict__ W,   // x_proj_w (rows 0..31 used)
    float* __restrict__ C)         // xdbl (cols 0..31), ldc=NXD
{
    int wid = threadIdx.x >> 5, lane = threadIdx.x & 31;
    int gw  = blockIdx.x * 8 + wid;      // 0..8191
    int rg  = gw >> 2;                   // row group: rows 4*rg..4*rg+3
    int cg  = gw & 3;                    // col group: cols 8*cg..8*cg+7
    int r0  = rg * 4;

    float acc[4][8];
#pragma unroll
    for (int r = 0; r < 4; r++)
#pragma unroll
        for (int c = 0; c < 8; c++) acc[r][c] = 0.f;

    const float* a0 = A + (size_t)r0 * D_INNER + lane;
    const float* w0 = W + (size_t)(cg * 8) * D_INNER + lane;

#pragma unroll 4
    for (int j = 0; j < 32; j++) {
        int k = j * 32;
        float av[4], wv[8];
#pragma unroll
        for (int r = 0; r < 4; r++) av[r] = a0[(size_t)r * D_INNER + k];
#pragma unroll
        for (int c = 0; c < 8; c++) wv[c] = w0[(size_t)c * D_INNER + k];
#pragma unroll
        for (int r = 0; r < 4; r++)
#pragma unroll
            for (int c = 0; c < 8; c++)
                acc[r][c] = fmaf(av[r], wv[c], acc[r][c]);
    }

#pragma unroll
    for (int r = 0; r < 4; r++)
#pragma unroll
        for (int c = 0; c < 8; c++) {
            float v = acc[r][c];
            v += __shfl_xor_sync(0xffffffffu, v, 16);
            v += __shfl_xor_sync(0xffffffffu, v, 8);
            v += __shfl_xor_sync(0xffffffffu, v, 4);
            v += __shfl_xor_sync(0xffffffffu, v, 2);
            v += __shfl_xor_sync(0xffffffffu, v, 1);
            acc[r][c] = v;
        }

    if (lane == 0) {
#pragma unroll
        for (int r = 0; r < 4; r++) {
            float4 lo = make_float4(acc[r][0], acc[r][1], acc[r][2], acc[r][3]);
            float4 hi = make_float4(acc[r][4], acc[r][5], acc[r][6], acc[r][7]);
            float* dst = C + (size_t)(r0 + r) * NXD + cg * 8;
            *(float4*)dst       = lo;
            *(float4*)(dst + 4) = hi;
        }
    }
}

// ---------------- generic fp32 GEMM (kept for dt_proj: accuracy) -----------
template<int EPI>
__global__ __launch_bounds__(256) void gemm_tn(
    const float* __restrict__ A, const float* __restrict__ B,
    float* __restrict__ C, const float* __restrict__ bias,
    int M, int N, int K, int lda, int ldb, int ldc)
{
    __shared__ float As[8][128];
    __shared__ float Bs[8][128];
    int tid  = threadIdx.x;
    int bm   = blockIdx.y * 128;
    int bn   = blockIdx.x * 128;
    int lrow = tid >> 1;
    int lk4  = (tid & 1) << 2;
    int tr   = tid >> 4;
    int tc   = tid & 15;

    float acc[8][8];
#pragma unroll
    for (int i = 0; i < 8; i++)
#pragma unroll
        for (int j = 0; j < 8; j++) acc[i][j] = 0.f;

    const float* Aptr = A + (size_t)(bm + lrow) * lda + lk4;
    const float* Bptr = B + (size_t)(bn + lrow) * ldb + lk4;
    bool bvalid = (bn + lrow) < N;

    for (int k0 = 0; k0 < K; k0 += 8) {
        float4 av = *(const float4*)(Aptr + k0);
        float4 bv = make_float4(0.f, 0.f, 0.f, 0.f);
        if (bvalid) bv = *(const float4*)(Bptr + k0);
        __syncthreads();
        As[lk4+0][lrow] = av.x; As[lk4+1][lrow] = av.y;
        As[lk4+2][lrow] = av.z; As[lk4+3][lrow] = av.w;
        Bs[lk4+0][lrow] = bv.x; Bs[lk4+1][lrow] = bv.y;
        Bs[lk4+2][lrow] = bv.z; Bs[lk4+3][lrow] = bv.w;
        __syncthreads();
#pragma unroll
        for (int k = 0; k < 8; k++) {
            float4 a0 = *(const float4*)&As[k][tr*8];
            float4 a1 = *(const float4*)&As[k][tr*8 + 4];
            float4 b0 = *(const float4*)&Bs[k][tc*8];
            float4 b1 = *(const float4*)&Bs[k][tc*8 + 4];
            float ar[8] = {a0.x,a0.y,a0.z,a0.w,a1.x,a1.y,a1.z,a1.w};
            float br[8] = {b0.x,b0.y,b0.z,b0.w,b1.x,b1.y,b1.z,b1.w};
#pragma unroll
            for (int i = 0; i < 8; i++)
#pragma unroll
                for (int j = 0; j < 8; j++)
                    acc[i][j] = fmaf(ar[i], br[j], acc[i][j]);
        }
    }
#pragma unroll
    for (int i = 0; i < 8; i++) {
        int r = bm + tr*8 + i;
#pragma unroll
        for (int j = 0; j < 8; j++) {
            int c = bn + tc*8 + j;
            if (c < N) {
                float v = acc[i][j];
                if (EPI == 1) {
                    v += bias[c];
                    v = (v > 0.f) ? v + log1pf(__expf(-v)) : log1pf(__expf(v));
                }
                C[(size_t)r * ldc + c] = v;
            }
        }
    }
}

// ---------------- causal depthwise conv (width 4) + SiLU -------------------
__global__ __launch_bounds__(256) void conv_silu_kernel(
    const float* __restrict__ xz, const float* __restrict__ cw,
    const float* __restrict__ cb, float* __restrict__ xc)
{
    int idx = blockIdx.x * 256 + threadIdx.x;
    int e = idx & (D_INNER - 1);
    int m = idx >> 10;
    int t = m & (SEQ - 1);
    float4 w = ((const float4*)cw)[e];
    const float* base = xz + (size_t)m * (2*D_INNER) + e;
    float acc = cb[e];
    acc = fmaf(base[0], w.w, acc);
    if (t >= 1) acc = fmaf(base[-(ptrdiff_t)(2*D_INNER)], w.z, acc);
    if (t >= 2) acc = fmaf(base[-(ptrdiff_t)(4*D_INNER)], w.y, acc);
    if (t >= 3) acc = fmaf(base[-(ptrdiff_t)(6*D_INNER)], w.x, acc);
    float sig = 1.f / (1.f + __expf(-acc));
    xc[idx] = acc * sig;
}

// ---------------- selective scan + fused gating epilogue -------------------
__global__ __launch_bounds__(256) void scan_kernel(
    const float* __restrict__ xdbl, const float* __restrict__ dt,
    const float* __restrict__ xc,   const float* __restrict__ xz,
    const float* __restrict__ A_log, const float* __restrict__ Dp,
    float* __restrict__ yout)
{
    __shared__ float sdt[32*8], sxc[32*8], sz[32*8], sy[32*8];
    int tid  = threadIdx.x;
    int b    = blockIdx.x >> 7;
    int e0   = (blockIdx.x & 127) << 3;
    int w    = tid >> 5;
    int lane = tid & 31;
    int e    = e0 + w;

    float A0 = -__expf(A_log[e*64 + 2*lane]);
    float A1 = -__expf(A_log[e*64 + 2*lane + 1]);
    float h0 = 0.f, h1 = 0.f;

    int tload = tid >> 3;
    int eload = tid & 7;
    size_t mbase = (size_t)b * SEQ;

    for (int t0 = 0; t0 < SEQ; t0 += 32) {
        size_t mrow = mbase + t0 + tload;
        sdt[tid] = dt[mrow * D_INNER + e0 + eload];
        sxc[tid] = xc[mrow * D_INNER + e0 + eload];
        sz[tid]  = xz[mrow * (2*D_INNER) + D_INNER + e0 + eload];
        __syncthreads();

        const float* xrow = xdbl + (mbase + t0) * NXD;
#pragma unroll 4
        for (int i = 0; i < 32; i++) {
            float dtv = sdt[i*8 + w];
            float xv  = sxc[i*8 + w];
            float2 Bv = *(const float2*)(xrow + DT_RANK + 2*lane);
            float2 Cv = *(const float2*)(xrow + DT_RANK + D_STATE + 2*lane);
            xrow += NXD;
            float du = dtv * xv;
            float g0 = __expf(dtv * A0);
            float g1 = __expf(dtv * A1);
            h0 = fmaf(g0, h0, du * Bv.x);
            h1 = fmaf(g1, h1, du * Bv.y);
            float p = fmaf(h0, Cv.x, h1 * Cv.y);
            p += __shfl_xor_sync(0xffffffffu, p, 16);
            p += __shfl_xor_sync(0xffffffffu, p, 8);
            p += __shfl_xor_sync(0xffffffffu, p, 4);
            p += __shfl_xor_sync(0xffffffffu, p, 2);
            p += __shfl_xor_sync(0xffffffffu, p, 1);
            if (lane == 0) sy[i*8 + w] = p;
        }
        __syncthreads();

        {
            float yv  = sy[tid];
            float xcv = sxc[tid];
            float zv  = sz[tid];
            float Dv  = Dp[e0 + eload];
            float r   = fmaf(Dv, xcv, yv);
            float sig = 1.f / (1.f + __expf(-zv));
            r = r * zv * sig;
            yout[mrow * D_INNER + e0 + eload] = r;
        }
        __syncthreads();
    }
}

// ---------------- host launch ----------------------------------------------
extern "C" void kernel_launch(void* const* d_in, const int* in_sizes, int n_in,
                              void* d_out, int out_size)
{
    const float* x         = (const float*)d_in[0];
    const float* ln_m_w    = (const float*)d_in[1];
    const float* ln_m_b    = (const float*)d_in[2];
    const float* ln1_w     = (const float*)d_in[3];
    const float* ln1_b     = (const float*)d_in[4];
    const float* in_proj_w = (const float*)d_in[5];
    const float* conv_w    = (const float*)d_in[6];
    const float* conv_b    = (const float*)d_in[7];
    const float* x_proj_w  = (const float*)d_in[8];
    const float* dt_proj_w = (const float*)d_in[9];
    const float* dt_proj_b = (const float*)d_in[10];
    const float* A_log     = (const float*)d_in[11];
    const float* D_param   = (const float*)d_in[12];
    const float* out_proj_w= (const float*)d_in[13];
    float* out = (float*)d_out;

    float *xn, *xz, *xc, *xdbl, *dtp, *y, *m;
    cudaGetSymbolAddress((void**)&xn,   g_xn);
    cudaGetSymbolAddress((void**)&xz,   g_xz);
    cudaGetSymbolAddress((void**)&xc,   g_xc);
    cudaGetSymbolAddress((void**)&xdbl, g_xdbl);
    cudaGetSymbolAddress((void**)&dtp,  g_dt);
    cudaGetSymbolAddress((void**)&y,    g_y);
    cudaGetSymbolAddress((void**)&m,    g_m);

    cudaFuncSetAttribute(gemm_tf32,
                         cudaFuncAttributeMaxDynamicSharedMemorySize, GEMM_SMEM);

    // 1. xn = LN(x)
    ln_kernel<<<M_TOT, 256>>>(x, ln_m_w, ln_m_b, nullptr, xn);

    // 2. xz = xn @ in_proj_w^T   [8192, 2048], K=512  (tf32)
    {
        dim3 g(2*D_INNER/128, M_TOT/128);
        gemm_tf32<<<g, 256, GEMM_SMEM>>>(xn, in_proj_w, xz, DIM, DIM, DIM, 2*D_INNER);
    }

    // 3. xc = silu(causal_conv(xp) + b)
    conv_silu_kernel<<<(M_TOT*D_INNER)/256, 256>>>(xz, conv_w, conv_b, xc);

    // 4a. dt_r = xc @ x_proj_w[0:32]^T   (fp32 — precision-critical exp path)
    dtr_kernel<<<M_TOT/8, 256>>>(xc, x_proj_w, xdbl);

    // 4b. B,C = xc @ x_proj_w[32:160]^T  (tf32 — linear path, N=128)
    {
        dim3 g(1, M_TOT/128);
        gemm_tf32<<<g, 256, GEMM_SMEM>>>(xc, x_proj_w + (size_t)DT_RANK*D_INNER,
                                         xdbl + DT_RANK, D_INNER, D_INNER, D_INNER, NXD);
    }

    // 5. dt = softplus(dt_r @ dt_proj_w^T + b)   [8192, 1024]  (fp32)
    {
        dim3 g(D_INNER/128, M_TOT/128);
        gemm_tn<1><<<g, 256>>>(xdbl, dt_proj_w, dtp, dt_proj_b,
                               M_TOT, D_INNER, DT_RANK, NXD, DT_RANK, D_INNER);
    }

    // 6. selective scan + gating
    scan_kernel<<<BSZ*128, 256>>>(xdbl, dtp, xc, xz, A_log, D_param, y);

    // 7. m = y @ out_proj_w^T   [8192, 512], K=1024  (tf32)
    {
        dim3 g(DIM/128, M_TOT/128);
        gemm_tf32<<<g, 256, GEMM_SMEM>>>(y, out_proj_w, m, D_INNER, D_INNER, D_INNER, DIM);
    }

    // 8. out = x + LN(m)
    ln_kernel<<<M_TOT, 256>>>(m, ln1_w, ln1_b, x, out);
}

// round 12
// speedup vs baseline: 1.6510x; 1.0114x over previous
#include <cuda_runtime.h>
#include <cuda_fp16.h>
#include <math.h>
#include <stdint.h>

#define DIM 512
#define D_INNER 1024
#define D_STATE 64
#define DT_RANK 32
#define NXD 160          // DT_RANK + 2*D_STATE
#define BSZ 4
#define SEQ 2048
#define M_TOT (BSZ*SEQ)  // 8192

// ---------------- scratch (device globals; no runtime allocation) ----------
__device__ float g_xn[(size_t)M_TOT*DIM];
__device__ float g_xz[(size_t)M_TOT*2*D_INNER];
__device__ float g_xc[(size_t)M_TOT*D_INNER];
__device__ float g_xdbl[(size_t)M_TOT*NXD];
__device__ float g_dt[(size_t)M_TOT*D_INNER];
__device__ float g_y[(size_t)M_TOT*D_INNER];
__device__ float g_m[(size_t)M_TOT*DIM];

// ---------------- layernorm (optionally + residual) ------------------------
__global__ __launch_bounds__(256) void ln_kernel(
    const float* __restrict__ x, const float* __restrict__ w,
    const float* __restrict__ b, const float* __restrict__ resid,
    float* __restrict__ out)
{
    int row = blockIdx.x;
    const float* xr = x + (size_t)row * DIM;
    int tid = threadIdx.x;
    float v0 = xr[tid];
    float v1 = xr[tid + 256];
    float s  = v0 + v1;
    float sq = v0*v0 + v1*v1;
#pragma unroll
    for (int o = 16; o > 0; o >>= 1) {
        s  += __shfl_xor_sync(0xffffffffu, s,  o);
        sq += __shfl_xor_sync(0xffffffffu, sq, o);
    }
    __shared__ float ss[8], ssq[8];
    int wid = tid >> 5, lane = tid & 31;
    if (lane == 0) { ss[wid] = s; ssq[wid] = sq; }
    __syncthreads();
    float st = 0.f, sqt = 0.f;
#pragma unroll
    for (int i = 0; i < 8; i++) { st += ss[i]; sqt += ssq[i]; }
    float mean = st * (1.f / DIM);
    float var  = sqt * (1.f / DIM) - mean * mean;
    float inv  = rsqrtf(var + 1e-5f);
    float r0 = (v0 - mean) * inv * w[tid]       + b[tid];
    float r1 = (v1 - mean) * inv * w[tid + 256] + b[tid + 256];
    if (resid) {
        r0 += resid[(size_t)row*DIM + tid];
        r1 += resid[(size_t)row*DIM + tid + 256];
    }
    out[(size_t)row*DIM + tid]       = r0;
    out[(size_t)row*DIM + tid + 256] = r1;
}

// ================= fp16 tensor-core GEMM: C[M,N] = A[M,K] * B[N,K]^T =======
// BM=BN=128, BK=16, 256 threads (8 warps 4x2), warp tile 32x64.
// mma.sync.m16n8k16.f32.f16.f16.f32; fp32->fp16 convert at STS time.
// Double-buffered via register prefetch. Requires M%128==0, N%128==0, K%16==0.
#define HSTR 24   // halves per smem row (16 + 8 pad); row = 48B, 16B-aligned

__device__ __forceinline__ void mma_h(float* d, const uint32_t* a, const uint32_t* b) {
    asm volatile(
        "mma.sync.aligned.m16n8k16.row.col.f32.f16.f16.f32 "
        "{%0,%1,%2,%3}, {%4,%5,%6,%7}, {%8,%9}, {%0,%1,%2,%3};"
        : "+f"(d[0]), "+f"(d[1]), "+f"(d[2]), "+f"(d[3])
        : "r"(a[0]), "r"(a[1]), "r"(a[2]), "r"(a[3]), "r"(b[0]), "r"(b[1]));
}
__device__ __forceinline__ void cvt_sts16(__half* dst, float4 lo, float4 hi) {
    __half2 h0 = __floats2half2_rn(lo.x, lo.y);
    __half2 h1 = __floats2half2_rn(lo.z, lo.w);
    __half2 h2 = __floats2half2_rn(hi.x, hi.y);
    __half2 h3 = __floats2half2_rn(hi.z, hi.w);
    uint4 v;
    v.x = *(uint32_t*)&h0; v.y = *(uint32_t*)&h1;
    v.z = *(uint32_t*)&h2; v.w = *(uint32_t*)&h3;
    *(uint4*)dst = v;
}

__global__ __launch_bounds__(256, 2) void gemm_h(
    const float* __restrict__ A, const float* __restrict__ B,
    float* __restrict__ C, int K, int lda, int ldb, int ldc)
{
    __shared__ __align__(16) __half As[2][128][HSTR];
    __shared__ __align__(16) __half Bs[2][128][HSTR];

    int tid  = threadIdx.x;
    int bm   = blockIdx.y * 128;
    int bn   = blockIdx.x * 128;
    int w    = tid >> 5, lane = tid & 31;
    int wm   = w & 3;
    int wn   = w >> 2;
    int gid  = lane >> 2;
    int tq   = lane & 3;

    int lrow = tid >> 1;
    int lk   = (tid & 1) * 8;
    const float* Ag = A + (size_t)(bm + lrow) * lda + lk;
    const float* Bg = B + (size_t)(bn + lrow) * ldb + lk;

    float acc[2][8][4];
#pragma unroll
    for (int i = 0; i < 2; i++)
#pragma unroll
        for (int j = 0; j < 8; j++)
#pragma unroll
            for (int q = 0; q < 4; q++) acc[i][j][q] = 0.f;

    int T = K / 16;

    // prologue: tile 0
    float4 ar0 = *(const float4*)Ag;
    float4 ar1 = *(const float4*)(Ag + 4);
    float4 br0 = *(const float4*)Bg;
    float4 br1 = *(const float4*)(Bg + 4);
    cvt_sts16(&As[0][lrow][lk], ar0, ar1);
    cvt_sts16(&Bs[0][lrow][lk], br0, br1);
    __syncthreads();

    for (int t = 0; t < T; t++) {
        int s = t & 1;
        if (t + 1 < T) {
            const float* ap = Ag + (size_t)(t + 1) * 16;
            const float* bp = Bg + (size_t)(t + 1) * 16;
            ar0 = *(const float4*)ap;
            ar1 = *(const float4*)(ap + 4);
            br0 = *(const float4*)bp;
            br1 = *(const float4*)(bp + 4);
        }

        uint32_t af[2][4];
        uint32_t bf[8][2];
#pragma unroll
        for (int mt = 0; mt < 2; mt++) {
            int m = wm * 32 + mt * 16;
            af[mt][0] = *(const uint32_t*)&As[s][m + gid    ][2*tq];
            af[mt][1] = *(const uint32_t*)&As[s][m + gid + 8][2*tq];
            af[mt][2] = *(const uint32_t*)&As[s][m + gid    ][2*tq + 8];
            af[mt][3] = *(const uint32_t*)&As[s][m + gid + 8][2*tq + 8];
        }
#pragma unroll
        for (int nt = 0; nt < 8; nt++) {
            int n = wn * 64 + nt * 8;
            bf[nt][0] = *(const uint32_t*)&Bs[s][n + gid][2*tq];
            bf[nt][1] = *(const uint32_t*)&Bs[s][n + gid][2*tq + 8];
        }
#pragma unroll
        for (int mt = 0; mt < 2; mt++)
#pragma unroll
            for (int nt = 0; nt < 8; nt++)
                mma_h(acc[mt][nt], af[mt], bf[nt]);

        if (t + 1 < T) {
            cvt_sts16(&As[s ^ 1][lrow][lk], ar0, ar1);
            cvt_sts16(&Bs[s ^ 1][lrow][lk], br0, br1);
        }
        __syncthreads();
    }

    // epilogue (same C mapping as m16n8k8)
#pragma unroll
    for (int mt = 0; mt < 2; mt++) {
        int r0 = bm + wm * 32 + mt * 16 + gid;
#pragma unroll
        for (int nt = 0; nt < 8; nt++) {
            int c = bn + wn * 64 + nt * 8 + tq * 2;
            float2 v01 = make_float2(acc[mt][nt][0], acc[mt][nt][1]);
            float2 v23 = make_float2(acc[mt][nt][2], acc[mt][nt][3]);
            *(float2*)&C[(size_t)r0 * ldc + c]       = v01;
            *(float2*)&C[(size_t)(r0 + 8) * ldc + c] = v23;
        }
    }
}

// ---------------- dt_r fp32 kernel: xdbl[:, 0:32] = xc @ x_proj_w[0:32]^T --
__global__ __launch_bounds__(256) void dtr_kernel(
    const float* __restrict__ A, const float* __restrict__ W,
    float* __restrict__ C)
{
    int wid = threadIdx.x >> 5, lane = threadIdx.x & 31;
    int gw  = blockIdx.x * 8 + wid;
    int rg  = gw >> 2;
    int cg  = gw & 3;
    int r0  = rg * 4;

    float acc[4][8];
#pragma unroll
    for (int r = 0; r < 4; r++)
#pragma unroll
        for (int c = 0; c < 8; c++) acc[r][c] = 0.f;

    const float* a0 = A + (size_t)r0 * D_INNER + lane;
    const float* w0 = W + (size_t)(cg * 8) * D_INNER + lane;

#pragma unroll 4
    for (int j = 0; j < 32; j++) {
        int k = j * 32;
        float av[4], wv[8];
#pragma unroll
        for (int r = 0; r < 4; r++) av[r] = a0[(size_t)r * D_INNER + k];
#pragma unroll
        for (int c = 0; c < 8; c++) wv[c] = w0[(size_t)c * D_INNER + k];
#pragma unroll
        for (int r = 0; r < 4; r++)
#pragma unroll
            for (int c = 0; c < 8; c++)
                acc[r][c] = fmaf(av[r], wv[c], acc[r][c]);
    }

#pragma unroll
    for (int r = 0; r < 4; r++)
#pragma unroll
        for (int c = 0; c < 8; c++) {
            float v = acc[r][c];
            v += __shfl_xor_sync(0xffffffffu, v, 16);
            v += __shfl_xor_sync(0xffffffffu, v, 8);
            v += __shfl_xor_sync(0xffffffffu, v, 4);
            v += __shfl_xor_sync(0xffffffffu, v, 2);
            v += __shfl_xor_sync(0xffffffffu, v, 1);
            acc[r][c] = v;
        }

    if (lane == 0) {
#pragma unroll
        for (int r = 0; r < 4; r++) {
            float4 lo = make_float4(acc[r][0], acc[r][1], acc[r][2], acc[r][3]);
            float4 hi = make_float4(acc[r][4], acc[r][5], acc[r][6], acc[r][7]);
            float* dst = C + (size_t)(r0 + r) * NXD + cg * 8;
            *(float4*)dst       = lo;
            *(float4*)(dst + 4) = hi;
        }
    }
}

// ---------------- generic fp32 GEMM (kept for dt_proj: accuracy) -----------
template<int EPI>
__global__ __launch_bounds__(256) void gemm_tn(
    const float* __restrict__ A, const float* __restrict__ B,
    float* __restrict__ C, const float* __restrict__ bias,
    int M, int N, int K, int lda, int ldb, int ldc)
{
    __shared__ float As[8][128];
    __shared__ float Bs[8][128];
    int tid  = threadIdx.x;
    int bm   = blockIdx.y * 128;
    int bn   = blockIdx.x * 128;
    int lrow = tid >> 1;
    int lk4  = (tid & 1) << 2;
    int tr   = tid >> 4;
    int tc   = tid & 15;

    float acc[8][8];
#pragma unroll
    for (int i = 0; i < 8; i++)
#pragma unroll
        for (int j = 0; j < 8; j++) acc[i][j] = 0.f;

    const float* Aptr = A + (size_t)(bm + lrow) * lda + lk4;
    const float* Bptr = B + (size_t)(bn + lrow) * ldb + lk4;
    bool bvalid = (bn + lrow) < N;

    for (int k0 = 0; k0 < K; k0 += 8) {
        float4 av = *(const float4*)(Aptr + k0);
        float4 bv = make_float4(0.f, 0.f, 0.f, 0.f);
        if (bvalid) bv = *(const float4*)(Bptr + k0);
        __syncthreads();
        As[lk4+0][lrow] = av.x; As[lk4+1][lrow] = av.y;
        As[lk4+2][lrow] = av.z; As[lk4+3][lrow] = av.w;
        Bs[lk4+0][lrow] = bv.x; Bs[lk4+1][lrow] = bv.y;
        Bs[lk4+2][lrow] = bv.z; Bs[lk4+3][lrow] = bv.w;
        __syncthreads();
#pragma unroll
        for (int k = 0; k < 8; k++) {
            float4 a0 = *(const float4*)&As[k][tr*8];
            float4 a1 = *(const float4*)&As[k][tr*8 + 4];
            float4 b0 = *(const float4*)&Bs[k][tc*8];
            float4 b1 = *(const float4*)&Bs[k][tc*8 + 4];
            float ar[8] = {a0.x,a0.y,a0.z,a0.w,a1.x,a1.y,a1.z,a1.w};
            float br[8] = {b0.x,b0.y,b0.z,b0.w,b1.x,b1.y,b1.z,b1.w};
#pragma unroll
            for (int i = 0; i < 8; i++)
#pragma unroll
                for (int j = 0; j < 8; j++)
                    acc[i][j] = fmaf(ar[i], br[j], acc[i][j]);
        }
    }
#pragma unroll
    for (int i = 0; i < 8; i++) {
        int r = bm + tr*8 + i;
#pragma unroll
        for (int j = 0; j < 8; j++) {
            int c = bn + tc*8 + j;
            if (c < N) {
                float v = acc[i][j];
                if (EPI == 1) {
                    v += bias[c];
                    v = (v > 0.f) ? v + log1pf(__expf(-v)) : log1pf(__expf(v));
                }
                C[(size_t)r * ldc + c] = v;
            }
        }
    }
}

// ---------------- causal depthwise conv (width 4) + SiLU -------------------
__global__ __launch_bounds__(256) void conv_silu_kernel(
    const float* __restrict__ xz, const float* __restrict__ cw,
    const float* __restrict__ cb, float* __restrict__ xc)
{
    int idx = blockIdx.x * 256 + threadIdx.x;
    int e = idx & (D_INNER - 1);
    int m = idx >> 10;
    int t = m & (SEQ - 1);
    float4 w = ((const float4*)cw)[e];
    const float* base = xz + (size_t)m * (2*D_INNER) + e;
    float acc = cb[e];
    acc = fmaf(base[0], w.w, acc);
    if (t >= 1) acc = fmaf(base[-(ptrdiff_t)(2*D_INNER)], w.z, acc);
    if (t >= 2) acc = fmaf(base[-(ptrdiff_t)(4*D_INNER)], w.y, acc);
    if (t >= 3) acc = fmaf(base[-(ptrdiff_t)(6*D_INNER)], w.x, acc);
    float sig = 1.f / (1.f + __expf(-acc));
    xc[idx] = acc * sig;
}

// ---------------- selective scan + fused gating epilogue -------------------
__global__ __launch_bounds__(256) void scan_kernel(
    const float* __restrict__ xdbl, const float* __restrict__ dt,
    const float* __restrict__ xc,   const float* __restrict__ xz,
    const float* __restrict__ A_log, const float* __restrict__ Dp,
    float* __restrict__ yout)
{
    __shared__ float sdt[32*8], sxc[32*8], sz[32*8], sy[32*8];
    int tid  = threadIdx.x;
    int b    = blockIdx.x >> 7;
    int e0   = (blockIdx.x & 127) << 3;
    int w    = tid >> 5;
    int lane = tid & 31;
    int e    = e0 + w;

    float A0 = -__expf(A_log[e*64 + 2*lane]);
    float A1 = -__expf(A_log[e*64 + 2*lane + 1]);
    float h0 = 0.f, h1 = 0.f;

    int tload = tid >> 3;
    int eload = tid & 7;
    size_t mbase = (size_t)b * SEQ;

    for (int t0 = 0; t0 < SEQ; t0 += 32) {
        size_t mrow = mbase + t0 + tload;
        sdt[tid] = dt[mrow * D_INNER + e0 + eload];
        sxc[tid] = xc[mrow * D_INNER + e0 + eload];
        sz[tid]  = xz[mrow * (2*D_INNER) + D_INNER + e0 + eload];
        __syncthreads();

        const float* xrow = xdbl + (mbase + t0) * NXD;
#pragma unroll 4
        for (int i = 0; i < 32; i++) {
            float dtv = sdt[i*8 + w];
            float xv  = sxc[i*8 + w];
            float2 Bv = *(const float2*)(xrow + DT_RANK + 2*lane);
            float2 Cv = *(const float2*)(xrow + DT_RANK + D_STATE + 2*lane);
            xrow += NXD;
            float du = dtv * xv;
            float g0 = __expf(dtv * A0);
            float g1 = __expf(dtv * A1);
            h0 = fmaf(g0, h0, du * Bv.x);
            h1 = fmaf(g1, h1, du * Bv.y);
            float p = fmaf(h0, Cv.x, h1 * Cv.y);
            p += __shfl_xor_sync(0xffffffffu, p, 16);
            p += __shfl_xor_sync(0xffffffffu, p, 8);
            p += __shfl_xor_sync(0xffffffffu, p, 4);
            p += __shfl_xor_sync(0xffffffffu, p, 2);
            p += __shfl_xor_sync(0xffffffffu, p, 1);
            if (lane == 0) sy[i*8 + w] = p;
        }
        __syncthreads();

        {
            float yv  = sy[tid];
            float xcv = sxc[tid];
            float zv  = sz[tid];
            float Dv  = Dp[e0 + eload];
            float r   = fmaf(Dv, xcv, yv);
            float sig = 1.f / (1.f + __expf(-zv));
            r = r * zv * sig;
            yout[mrow * D_INNER + e0 + eload] = r;
        }
        __syncthreads();
    }
}

// ---------------- host launch ----------------------------------------------
extern "C" void kernel_launch(void* const* d_in, const int* in_sizes, int n_in,
                              void* d_out, int out_size)
{
    const float* x         = (const float*)d_in[0];
    const float* ln_m_w    = (const float*)d_in[1];
    const float* ln_m_b    = (const float*)d_in[2];
    const float* ln1_w     = (const float*)d_in[3];
    const float* ln1_b     = (const float*)d_in[4];
    const float* in_proj_w = (const float*)d_in[5];
    const float* conv_w    = (const float*)d_in[6];
    const float* conv_b    = (const float*)d_in[7];
    const float* x_proj_w  = (const float*)d_in[8];
    const float* dt_proj_w = (const float*)d_in[9];
    const float* dt_proj_b = (const float*)d_in[10];
    const float* A_log     = (const float*)d_in[11];
    const float* D_param   = (const float*)d_in[12];
    const float* out_proj_w= (const float*)d_in[13];
    float* out = (float*)d_out;

    float *xn, *xz, *xc, *xdbl, *dtp, *y, *m;
    cudaGetSymbolAddress((void**)&xn,   g_xn);
    cudaGetSymbolAddress((void**)&xz,   g_xz);
    cudaGetSymbolAddress((void**)&xc,   g_xc);
    cudaGetSymbolAddress((void**)&xdbl, g_xdbl);
    cudaGetSymbolAddress((void**)&dtp,  g_dt);
    cudaGetSymbolAddress((void**)&y,    g_y);
    cudaGetSymbolAddress((void**)&m,    g_m);

    // 1. xn = LN(x)
    ln_kernel<<<M_TOT, 256>>>(x, ln_m_w, ln_m_b, nullptr, xn);

    // 2. xz = xn @ in_proj_w^T   [8192, 2048], K=512  (fp16 mma)
    {
        dim3 g(2*D_INNER/128, M_TOT/128);
        gemm_h<<<g, 256>>>(xn, in_proj_w, xz, DIM, DIM, DIM, 2*D_INNER);
    }

    // 3. xc = silu(causal_conv(xp) + b)
    conv_silu_kernel<<<(M_TOT*D_INNER)/256, 256>>>(xz, conv_w, conv_b, xc);

    // 4a. dt_r = xc @ x_proj_w[0:32]^T   (fp32 — precision-critical exp path)
    dtr_kernel<<<M_TOT/8, 256>>>(xc, x_proj_w, xdbl);

    // 4b. B,C = xc @ x_proj_w[32:160]^T  (fp16 mma, N=128)
    {
        dim3 g(1, M_TOT/128);
        gemm_h<<<g, 256>>>(xc, x_proj_w + (size_t)DT_RANK*D_INNER,
                           xdbl + DT_RANK, D_INNER, D_INNER, D_INNER, NXD);
    }

    // 5. dt = softplus(dt_r @ dt_proj_w^T + b)   [8192, 1024]  (fp32)
    {
        dim3 g(D_INNER/128, M_TOT/128);
        gemm_tn<1><<<g, 256>>>(xdbl, dt_proj_w, dtp, dt_proj_b,
                               M_TOT, D_INNER, DT_RANK, NXD, DT_RANK, D_INNER);
    }

    // 6. selective scan + gating
    scan_kernel<<<BSZ*128, 256>>>(xdbl, dtp, xc, xz, A_log, D_param, y);

    // 7. m = y @ out_proj_w^T   [8192, 512], K=1024  (fp16 mma)
    {
        dim3 g(DIM/128, M_TOT/128);
        gemm_h<<<g, 256>>>(y, out_proj_w, m, D_INNER, D_INNER, D_INNER, DIM);
    }

    // 8. out = x + LN(m)
    ln_kernel<<<M_TOT, 256>>>(m, ln1_w, ln1_b, x, out);
}